// round 13
// baseline (speedup 1.0000x reference)
#include <cuda_runtime.h>

#define NN 100000
#define EE 1600000
#define DD 64
#define HH 64
#define GG 64
#define CC 2

// ---- scratch (device globals; referenced ONLY inside device code) ----
__device__ __align__(16) float d_hbuf[NN * HH];   // layer activations h
__device__ __align__(16) float d_gbuf[NN * HH];   // g = (h@W)*dinv
__device__ int   d_cnt[NN];        // in-degree (int)
__device__ int   d_rowstart[NN + 1];
__device__ int   d_cursor[NN];
__device__ int   d_csrsrc[EE];     // src node per edge, grouped by dst
__device__ float d_sums[GG * HH];
__device__ float d_cnts[GG];

// ---------------------------------------------------------------------------
__global__ void k_zero_cnt() {
    int i = blockIdx.x * blockDim.x + threadIdx.x;
    if (i < NN) d_cnt[i] = 0;
}

__global__ void k_count(const int* __restrict__ edge_index) {
    int e = blockIdx.x * blockDim.x + threadIdx.x;
    if (e < EE) {
        int dst = edge_index[EE + e];
        if ((unsigned)dst < NN) atomicAdd(&d_cnt[dst], 1);
    }
}

// single-block exclusive scan of d_cnt -> d_rowstart (also seeds d_cursor)
#define SCAN_T 1024
__global__ void k_scan() {
    __shared__ int ssum[SCAN_T];
    int t = threadIdx.x;
    const int per = (NN + SCAN_T - 1) / SCAN_T;   // 98
    int lo = t * per;
    int hi = lo + per < NN ? lo + per : NN;

    int s = 0;
    for (int i = lo; i < hi; i++) s += d_cnt[i];
    ssum[t] = s;
    __syncthreads();

    // inclusive Hillis-Steele scan over ssum
    for (int off = 1; off < SCAN_T; off <<= 1) {
        int v = 0;
        if (t >= off) v = ssum[t - off];
        __syncthreads();
        if (t >= off) ssum[t] += v;
        __syncthreads();
    }

    int run = ssum[t] - s;   // exclusive prefix for this segment
    for (int i = lo; i < hi; i++) {
        d_rowstart[i] = run;
        d_cursor[i] = run;
        run += d_cnt[i];
    }
    if (t == SCAN_T - 1) d_rowstart[NN] = run;
}

__global__ void k_fill(const int* __restrict__ edge_index) {
    int e = blockIdx.x * blockDim.x + threadIdx.x;
    if (e < EE) {
        int src = edge_index[e];
        int dst = edge_index[EE + e];
        if ((unsigned)src >= NN || (unsigned)dst >= NN) return;
        int pos = atomicAdd(&d_cursor[dst], 1);
        d_csrsrc[pos] = src;
    }
}

// ---------------------------------------------------------------------------
// GEMM: g[row] = (X[row] @ W) * rsqrt(deg+1)
// FIRST: X = external input x; else X = d_hbuf (device-side reference only —
// passing the global as a host-side arg yields the host shadow address).
// 256 threads, 64 rows/block, 4x4 register tile per thread.
template <bool FIRST>
__global__ void k_gemm(const float* __restrict__ Xext,
                       const float* __restrict__ W) {
    __shared__ float Xs[64][65];
    __shared__ __align__(16) float Ws[64 * 64];

    int tid = threadIdx.x;
    int row0 = blockIdx.x * 64;
    const float* X = FIRST ? Xext : (const float*)d_hbuf;

    #pragma unroll
    for (int i = 0; i < 16; i++)
        Ws[tid + i * 256] = W[tid + i * 256];

    #pragma unroll
    for (int i = 0; i < 16; i++) {
        int idx = tid + i * 256;
        int r = idx >> 6, c = idx & 63;
        int grow = row0 + r;
        Xs[r][c] = (grow < NN) ? X[grow * 64 + c] : 0.0f;
    }
    __syncthreads();

    int txg = tid & 15;
    int ty  = tid >> 4;

    float a0x = 0, a0y = 0, a0z = 0, a0w = 0;
    float a1x = 0, a1y = 0, a1z = 0, a1w = 0;
    float a2x = 0, a2y = 0, a2z = 0, a2w = 0;
    float a3x = 0, a3y = 0, a3z = 0, a3w = 0;

    #pragma unroll
    for (int k = 0; k < 64; k++) {
        float4 w = reinterpret_cast<const float4*>(Ws)[k * 16 + txg];
        float x0 = Xs[ty * 4 + 0][k];
        float x1 = Xs[ty * 4 + 1][k];
        float x2 = Xs[ty * 4 + 2][k];
        float x3 = Xs[ty * 4 + 3][k];
        a0x = fmaf(x0, w.x, a0x); a0y = fmaf(x0, w.y, a0y);
        a0z = fmaf(x0, w.z, a0z); a0w = fmaf(x0, w.w, a0w);
        a1x = fmaf(x1, w.x, a1x); a1y = fmaf(x1, w.y, a1y);
        a1z = fmaf(x1, w.z, a1z); a1w = fmaf(x1, w.w, a1w);
        a2x = fmaf(x2, w.x, a2x); a2y = fmaf(x2, w.y, a2y);
        a2z = fmaf(x2, w.z, a2z); a2w = fmaf(x2, w.w, a2w);
        a3x = fmaf(x3, w.x, a3x); a3y = fmaf(x3, w.y, a3y);
        a3z = fmaf(x3, w.z, a3z); a3w = fmaf(x3, w.w, a3w);
    }

    #pragma unroll
    for (int r = 0; r < 4; r++) {
        int grow = row0 + ty * 4 + r;
        if (grow >= NN) continue;
        float dinv = rsqrtf((float)d_cnt[grow] + 1.0f);
        float4 v;
        if (r == 0) v = make_float4(a0x, a0y, a0z, a0w);
        else if (r == 1) v = make_float4(a1x, a1y, a1z, a1w);
        else if (r == 2) v = make_float4(a2x, a2y, a2z, a2w);
        else v = make_float4(a3x, a3y, a3z, a3w);
        v.x *= dinv; v.y *= dinv; v.z *= dinv; v.w *= dinv;
        reinterpret_cast<float4*>(d_gbuf)[grow * 16 + txg] = v;
    }
}

// ---------------------------------------------------------------------------
// CSR gather aggregation (NO atomics):
// h[n] = relu( (g[n] + sum_{src in in(n)} g[src]) * dinv[n] + b )
// 16 threads per node (one float4 chunk each); 16 nodes per block.
__global__ void k_aggr(const float* __restrict__ b) {
    int t = blockIdx.x * blockDim.x + threadIdx.x;
    int n = t >> 4;
    int q = t & 15;
    if (n >= NN) return;

    const float4* g4 = reinterpret_cast<const float4*>(d_gbuf);
    float4 acc = g4[n * 16 + q];               // self-loop term

    int s = d_rowstart[n];
    int e = d_rowstart[n + 1];
    for (int i = s; i < e; i++) {
        int src = d_csrsrc[i];                  // broadcast across 16 threads
        float4 v = g4[src * 16 + q];
        acc.x += v.x; acc.y += v.y; acc.z += v.z; acc.w += v.w;
    }

    float dinv = rsqrtf((float)(e - s) + 1.0f);
    const float4 bb = reinterpret_cast<const float4*>(b)[q];
    float4 h;
    h.x = fmaxf(fmaf(acc.x, dinv, bb.x), 0.0f);
    h.y = fmaxf(fmaf(acc.y, dinv, bb.y), 0.0f);
    h.z = fmaxf(fmaf(acc.z, dinv, bb.z), 0.0f);
    h.w = fmaxf(fmaf(acc.w, dinv, bb.w), 0.0f);
    reinterpret_cast<float4*>(d_hbuf)[n * 16 + q] = h;
}

// ---------------------------------------------------------------------------
__global__ void k_zero_pool() {
    int i = blockIdx.x * blockDim.x + threadIdx.x;
    if (i < GG * HH) d_sums[i] = 0.0f;
    if (i < GG) d_cnts[i] = 0.0f;
}

// mean-pool numerators: one column x 16 consecutive nodes per thread,
// run-accumulate per graph (batch sorted), one atomic per run.
#define POOL_NPT 16
__global__ void k_pool(const int* __restrict__ batch) {
    int t = blockIdx.x * blockDim.x + threadIdx.x;
    int c = t & 63;
    int nb = t >> 6;
    int n0 = nb * POOL_NPT;
    if (n0 >= NN) return;

    int cur = -1;
    float s = 0.0f;
    float cnt = 0.0f;
    #pragma unroll
    for (int i = 0; i < POOL_NPT; i++) {
        int n = n0 + i;
        if (n >= NN) break;
        int g = batch[n];
        if (g != cur) {
            if (cur >= 0 && (unsigned)cur < GG) {
                atomicAdd(&d_sums[cur * 64 + c], s);
                if (c == 0) atomicAdd(&d_cnts[cur], cnt);
            }
            cur = g; s = 0.0f; cnt = 0.0f;
        }
        s += d_hbuf[n * 64 + c];
        cnt += 1.0f;
    }
    if (cur >= 0 && (unsigned)cur < GG) {
        atomicAdd(&d_sums[cur * 64 + c], s);
        if (c == 0) atomicAdd(&d_cnts[cur], cnt);
    }
}

__global__ void k_final(const float* __restrict__ Wlin,
                        const float* __restrict__ blin,
                        float* __restrict__ out) {
    int t = threadIdx.x;
    if (t < GG * CC) {
        int g = t / CC, c = t % CC;
        float inv = 1.0f / fmaxf(d_cnts[g], 1.0f);
        float acc = blin[c];
        #pragma unroll
        for (int h = 0; h < HH; h++)
            acc = fmaf(d_sums[g * 64 + h] * inv, Wlin[h * CC + c], acc);
        out[g * CC + c] = acc;
    }
}

// ---------------------------------------------------------------------------
extern "C" void kernel_launch(void* const* d_in, const int* in_sizes, int n_in,
                              void* d_out, int out_size) {
    const float* x    = (const float*)d_in[0];
    const int*   ei   = (const int*)  d_in[1];
    const int*   batch= (const int*)  d_in[2];
    const float* W0   = (const float*)d_in[3];
    const float* b0   = (const float*)d_in[4];
    const float* W1   = (const float*)d_in[5];
    const float* b1   = (const float*)d_in[6];
    const float* W2   = (const float*)d_in[7];
    const float* b2   = (const float*)d_in[8];
    const float* Wlin = (const float*)d_in[9];
    const float* blin = (const float*)d_in[10];
    float* out = (float*)d_out;

    const int gemmB = (NN + 63) / 64;
    const int nodeB = (NN + 255) / 256;
    const int edgeB = (EE + 255) / 256;
    const int aggrB = (NN * 16 + 255) / 256;     // 6250
    const int poolB = (((NN + POOL_NPT - 1) / POOL_NPT) * 64 + 255) / 256;

    // ---- CSR build (amortized over 3 layers) ----
    k_zero_cnt<<<nodeB, 256>>>();
    k_count<<<edgeB, 256>>>(ei);
    k_scan<<<1, SCAN_T>>>();
    k_fill<<<edgeB, 256>>>(ei);

    // layer 0
    k_gemm<true><<<gemmB, 256>>>(x, W0);
    k_aggr<<<aggrB, 256>>>(b0);

    // layer 1
    k_gemm<false><<<gemmB, 256>>>(nullptr, W1);
    k_aggr<<<aggrB, 256>>>(b1);

    // layer 2
    k_gemm<false><<<gemmB, 256>>>(nullptr, W2);
    k_aggr<<<aggrB, 256>>>(b2);

    // pooling + head
    k_zero_pool<<<(GG * HH + 255) / 256, 256>>>();
    k_pool<<<poolB, 256>>>(batch);
    k_final<<<1, 128>>>(Wlin, blin, out);
}